// round 1
// baseline (speedup 1.0000x reference)
#include <cuda_runtime.h>

#define NN 50000
#define DD 256
#define GG 64
#define DOUT 16

// ---------------- scratch (static device memory; no allocation) ----------------
__device__ float g_S0[NN * DD];     // tmp = in @ W
__device__ float g_S1[NN * DD];     // agg / layer output (in-place relu)
__device__ float g_deg[NN];
__device__ float g_dinv[NN];
__device__ float g_pool[GG * DD];
__device__ float g_cnt[GG];
__device__ int   g_flags[2];        // [0]: edge_index is int32, [1]: batch is int32

// ---------------- index dtype handling ----------------
__device__ __forceinline__ long long fetch_idx(const void* p, long long i, int is32) {
    if (is32) return (long long)((const int*)p)[i];
    return ((const long long*)p)[i];
}

__global__ void k_zero_misc() {
    int i = blockIdx.x * blockDim.x + threadIdx.x;
    if (i < NN) g_deg[i] = 0.f;
    if (i < GG * DD) g_pool[i] = 0.f;
    if (i < GG) g_cnt[i] = 0.f;
    if (i < 2) g_flags[i] = 0;
}

// If the buffer is int64, all odd 32-bit words (high halves of values < 2^31)
// are zero. If int32, odd words are actual random index values -> some nonzero.
__global__ void k_detect(const unsigned* __restrict__ w, long long nwords, int which) {
    long long i = 2ll * ((long long)blockIdx.x * blockDim.x + threadIdx.x) + 1;
    unsigned v = (i < nwords) ? w[i] : 0u;
#pragma unroll
    for (int o = 16; o > 0; o >>= 1) v |= __shfl_xor_sync(0xffffffffu, v, o);
    if ((threadIdx.x & 31) == 0 && v) atomicOr(&g_flags[which], 1);
}

__global__ void k_deg(const void* __restrict__ ei, long long E) {
    long long e = (long long)blockIdx.x * blockDim.x + threadIdx.x;
    if (e >= E) return;
    int is32 = g_flags[0];
    long long d = fetch_idx(ei, E + e, is32);
    atomicAdd(&g_deg[d], 1.0f);
}

__global__ void k_dinv() {
    int n = blockIdx.x * blockDim.x + threadIdx.x;
    if (n < NN) g_dinv[n] = rsqrtf(g_deg[n] + 1.0f);  // +1 self-loop
}

// ---------------- SGEMM: C[M,256] = A[M,256] @ B[256,256] ----------------
#define BM 64
#define BN 64
#define BK 16
__global__ void k_sgemm(const float* __restrict__ A, const float* __restrict__ B,
                        float* __restrict__ C, int M) {
    __shared__ __align__(16) float As[BK][BM];
    __shared__ __align__(16) float Bs[BK][BN];
    int bm = blockIdx.x * BM, bn = blockIdx.y * BN;
    int tid = threadIdx.x;              // 256 threads
    int tr = tid >> 4, tc = tid & 15;   // 16 x 16, each does 4x4
    float acc[4][4] = {};

    for (int k0 = 0; k0 < DD; k0 += BK) {
#pragma unroll
        for (int i = 0; i < 4; i++) {
            int idx = tid + i * 256;    // 0..1023
            int row = idx >> 4;         // /BK
            int kk  = idx & 15;
            int grow = bm + row;
            As[kk][row] = (grow < M) ? A[(long long)grow * DD + k0 + kk] : 0.f;
        }
#pragma unroll
        for (int i = 0; i < 4; i++) {
            int idx = tid + i * 256;
            int kk  = idx >> 6;
            int col = idx & 63;
            Bs[kk][col] = B[(long long)(k0 + kk) * DD + bn + col];
        }
        __syncthreads();
#pragma unroll
        for (int kk = 0; kk < BK; kk++) {
            float4 a4 = *(const float4*)&As[kk][tr * 4];
            float4 b4 = *(const float4*)&Bs[kk][tc * 4];
            float av[4] = {a4.x, a4.y, a4.z, a4.w};
            float bv[4] = {b4.x, b4.y, b4.z, b4.w};
#pragma unroll
            for (int i2 = 0; i2 < 4; i2++)
#pragma unroll
                for (int j = 0; j < 4; j++) acc[i2][j] += av[i2] * bv[j];
        }
        __syncthreads();
    }
#pragma unroll
    for (int i = 0; i < 4; i++) {
        int grow = bm + tr * 4 + i;
        if (grow < M) {
            float4 v = {acc[i][0], acc[i][1], acc[i][2], acc[i][3]};
            *(float4*)&C[(long long)grow * DD + bn + tc * 4] = v;
        }
    }
}

// agg[n] = tmp[n] * dinv[n]^2   (self-loop term; also serves as the zero-init)
__global__ void k_init_agg(const float* __restrict__ tmp, float* __restrict__ agg) {
    int i = blockIdx.x * blockDim.x + threadIdx.x;   // NN * 64 (float4 per thread)
    if (i >= NN * (DD / 4)) return;
    int n = i >> 6;
    int c = (i & 63) * 4;
    float di = g_dinv[n];
    float s = di * di;
    float4 v = *(const float4*)(tmp + (long long)n * DD + c);
    float4 o = {v.x * s, v.y * s, v.z * s, v.w * s};
    *(float4*)(agg + (long long)n * DD + c) = o;
}

// agg[dst] += tmp[src] * dinv[src]*dinv[dst]   (64 threads per edge, float4 each)
__global__ void k_scatter(const float* __restrict__ tmp, float* __restrict__ agg,
                          const void* __restrict__ ei, long long E) {
    long long e = (long long)blockIdx.x * 4 + (threadIdx.x >> 6);
    if (e >= E) return;
    int c = (threadIdx.x & 63) * 4;
    int is32 = g_flags[0];
    long long s = fetch_idx(ei, e, is32);
    long long d = fetch_idx(ei, E + e, is32);
    float norm = g_dinv[s] * g_dinv[d];
    float4 v = *(const float4*)(tmp + s * DD + c);
    float* o = agg + d * DD + c;
    atomicAdd(o + 0, v.x * norm);
    atomicAdd(o + 1, v.y * norm);
    atomicAdd(o + 2, v.z * norm);
    atomicAdd(o + 3, v.w * norm);
}

__global__ void k_bias_relu(float* __restrict__ h, const float* __restrict__ b) {
    long long i = (long long)blockIdx.x * blockDim.x + threadIdx.x;
    if (i >= (long long)NN * DD) return;
    int c = (int)(i & (DD - 1));
    float v = h[i] + b[c];
    h[i] = v > 0.f ? v : 0.f;
}

__global__ void k_pool(const float* __restrict__ h, const void* __restrict__ batch) {
    int i = blockIdx.x * blockDim.x + threadIdx.x;   // NN * 64 (float4 per thread)
    if (i >= NN * (DD / 4)) return;
    int n = i >> 6;
    int c = (i & 63) * 4;
    int is32 = g_flags[1];
    long long g = fetch_idx(batch, n, is32);
    float4 v = *(const float4*)(h + (long long)n * DD + c);
    float* o = g_pool + g * DD + c;
    atomicAdd(o + 0, v.x);
    atomicAdd(o + 1, v.y);
    atomicAdd(o + 2, v.z);
    atomicAdd(o + 3, v.w);
    if ((i & 63) == 0) atomicAdd(&g_cnt[g], 1.0f);
}

__global__ void k_fc(const float* __restrict__ Wfc, const float* __restrict__ bfc,
                     float* __restrict__ out) {
    int t = blockIdx.x * blockDim.x + threadIdx.x;
    if (t >= GG * DOUT) return;
    int g = t >> 4, o = t & 15;
    float inv = 1.0f / fmaxf(g_cnt[g], 1.0f);
    float acc = 0.f;
#pragma unroll 8
    for (int k = 0; k < DD; k++) acc += g_pool[g * DD + k] * Wfc[k * DOUT + o];
    out[t] = acc * inv + bfc[o];   // (sum/cnt)@W == (sum@W)/cnt
}

// ---------------- launch ----------------
extern "C" void kernel_launch(void* const* d_in, const int* in_sizes, int n_in,
                              void* d_out, int out_size) {
    const float* x    = (const float*)d_in[0];
    const void*  ei   = d_in[1];
    const void*  batch = d_in[2];
    const float* W1 = (const float*)d_in[3];  const float* b1 = (const float*)d_in[4];
    const float* W2 = (const float*)d_in[5];  const float* b2 = (const float*)d_in[6];
    const float* W3 = (const float*)d_in[7];  const float* b3 = (const float*)d_in[8];
    const float* Wfc = (const float*)d_in[9]; const float* bfc = (const float*)d_in[10];
    float* out = (float*)d_out;

    long long E = in_sizes[1] / 2;   // 400000 (element count is 2E for either dtype)

    float *S0, *S1;
    cudaGetSymbolAddress((void**)&S0, g_S0);
    cudaGetSymbolAddress((void**)&S1, g_S1);

    k_zero_misc<<<(NN + 255) / 256, 256>>>();
    k_detect<<<(int)((in_sizes[1] / 2 + 255) / 256), 256>>>((const unsigned*)ei,
                                                            (long long)in_sizes[1], 0);
    k_detect<<<(int)((in_sizes[2] / 2 + 255) / 256), 256>>>((const unsigned*)batch,
                                                            (long long)in_sizes[2], 1);
    k_deg<<<(int)((E + 255) / 256), 256>>>(ei, E);
    k_dinv<<<(NN + 255) / 256, 256>>>();

    dim3 gemm_grid((NN + BM - 1) / BM, DD / BN);
    const float* Ws[3] = {W1, W2, W3};
    const float* bs[3] = {b1, b2, b3};
    const float* in = x;
    for (int l = 0; l < 3; l++) {
        k_sgemm<<<gemm_grid, 256>>>(in, Ws[l], S0, NN);
        k_init_agg<<<(NN * 64 + 255) / 256, 256>>>(S0, S1);
        k_scatter<<<(int)((E + 3) / 4), 256>>>(S0, S1, ei, E);
        k_bias_relu<<<(int)(((long long)NN * DD + 255) / 256), 256>>>(S1, bs[l]);
        in = S1;
    }

    k_pool<<<(NN * 64 + 255) / 256, 256>>>(S1, batch);
    k_fc<<<(GG * DOUT + 255) / 256, 256>>>(Wfc, bfc, out);
}

// round 2
// speedup vs baseline: 2.6642x; 2.6642x over previous
#include <cuda_runtime.h>
#include <cstdint>

#define NN 50000
#define EE 400000
#define DD 256
#define GG 64
#define DOUT 16

// ---------------- static scratch ----------------
__device__ float g_S0[NN * DD];       // tmp = in @ W
__device__ float g_S1[NN * DD];       // layer output
__device__ int   g_degi[NN];
__device__ float g_dinv[NN];
__device__ int   g_rowptr[NN + 1];
__device__ int   g_cursor[NN];
__device__ int   g_csr_src[EE];
__device__ float g_csr_w[EE];
__device__ float g_pool[GG * DD];
__device__ float g_cnt[GG];
__device__ int   g_flags[2];          // [0]: edge_index is32, [1]: batch is32

// ---------------- index dtype ----------------
__device__ __forceinline__ long long fetch_idx(const void* p, long long i, int is32) {
    if (is32) return (long long)((const int*)p)[i];
    return ((const long long*)p)[i];
}

__global__ void k_zero_misc() {
    int i = blockIdx.x * blockDim.x + threadIdx.x;
    if (i < NN) g_degi[i] = 0;
    if (i < GG * DD) g_pool[i] = 0.f;
    if (i < GG) g_cnt[i] = 0.f;
    if (i < 2) g_flags[i] = 0;
}

// int64 values < 2^31 have zero high words; int32 buffers have nonzero odd words.
__global__ void k_detect(const unsigned* __restrict__ w, long long nwords, int which) {
    long long i = 2ll * ((long long)blockIdx.x * blockDim.x + threadIdx.x) + 1;
    unsigned v = (i < nwords) ? w[i] : 0u;
#pragma unroll
    for (int o = 16; o > 0; o >>= 1) v |= __shfl_xor_sync(0xffffffffu, v, o);
    if ((threadIdx.x & 31) == 0 && v) atomicOr(&g_flags[which], 1);
}

__global__ void k_count(const void* __restrict__ ei, long long E) {
    long long e = (long long)blockIdx.x * blockDim.x + threadIdx.x;
    if (e >= E) return;
    int is32 = g_flags[0];
    long long d = fetch_idx(ei, E + e, is32);
    atomicAdd(&g_degi[d], 1);
}

__global__ void k_dinv() {
    int n = blockIdx.x * blockDim.x + threadIdx.x;
    if (n < NN) g_dinv[n] = rsqrtf((float)g_degi[n] + 1.0f);   // +1 self loop
}

// Single-block exclusive scan over 50000 degrees -> row_ptr + cursor
__global__ void k_scan() {
    __shared__ int part[1024];
    const int CH = (NN + 1023) / 1024;   // 49
    int t = threadIdx.x;
    int beg = t * CH, end = min(beg + CH, NN);
    int s = 0;
    for (int i = beg; i < end; i++) s += g_degi[i];
    part[t] = s;
    __syncthreads();
    for (int off = 1; off < 1024; off <<= 1) {
        int v = (t >= off) ? part[t - off] : 0;
        __syncthreads();
        part[t] += v;
        __syncthreads();
    }
    int excl = (t == 0) ? 0 : part[t - 1];
    for (int i = beg; i < end; i++) {
        g_rowptr[i] = excl;
        g_cursor[i] = excl;
        excl += g_degi[i];
    }
    if (t == 1023) g_rowptr[NN] = part[1023];
}

__global__ void k_fill(const void* __restrict__ ei, long long E) {
    long long e = (long long)blockIdx.x * blockDim.x + threadIdx.x;
    if (e >= E) return;
    int is32 = g_flags[0];
    int s = (int)fetch_idx(ei, e, is32);
    int d = (int)fetch_idx(ei, E + e, is32);
    int pos = atomicAdd(&g_cursor[d], 1);
    g_csr_src[pos] = s;
    g_csr_w[pos] = g_dinv[s] * g_dinv[d];
}

// ---------------- 3xTF32 tensor-core GEMM: C[M,256] = A[M,256] @ B[256,256] ----
__device__ __forceinline__ void split_tf32(float x, uint32_t& hi, uint32_t& lo) {
    asm("cvt.rna.tf32.f32 %0, %1;" : "=r"(hi) : "f"(x));
    float r = x - __uint_as_float(hi);
    asm("cvt.rna.tf32.f32 %0, %1;" : "=r"(lo) : "f"(r));
}

__device__ __forceinline__ void mma8(float* c, const uint32_t* a, const uint32_t* b) {
    asm volatile(
        "mma.sync.aligned.m16n8k8.row.col.f32.tf32.tf32.f32 "
        "{%0,%1,%2,%3}, {%4,%5,%6,%7}, {%8,%9}, {%0,%1,%2,%3};"
        : "+f"(c[0]), "+f"(c[1]), "+f"(c[2]), "+f"(c[3])
        : "r"(a[0]), "r"(a[1]), "r"(a[2]), "r"(a[3]), "r"(b[0]), "r"(b[1]));
}

// block 256 threads = 8 warps; warp tile 32(m) x 64(n); block tile 256m x 64n.
__global__ __launch_bounds__(256) void k_gemm_tf32(const float* __restrict__ A,
                                                   const float* __restrict__ B,
                                                   float* __restrict__ C, int M) {
    int wid = threadIdx.x >> 5, lane = threadIdx.x & 31;
    int g = lane >> 2, t = lane & 3;
    int nb = blockIdx.y * 64;
    int r0 = blockIdx.x * 256 + wid * 32 + g;

    int rows[4] = {r0, r0 + 8, r0 + 16, r0 + 24};
    bool vr[4];
    const float* ap[4];
#pragma unroll
    for (int i = 0; i < 4; i++) {
        vr[i] = rows[i] < M;
        ap[i] = A + (long long)(vr[i] ? rows[i] : 0) * DD;
    }

    float acc[2][8][4];
#pragma unroll
    for (int i = 0; i < 2; i++)
#pragma unroll
        for (int j = 0; j < 8; j++)
#pragma unroll
            for (int q = 0; q < 4; q++) acc[i][j][q] = 0.f;

    for (int k0 = 0; k0 < DD; k0 += 8) {
        uint32_t ah[2][4], al[2][4];
#pragma unroll
        for (int i = 0; i < 2; i++) {
            float f0 = vr[2 * i]     ? ap[2 * i][k0 + t]         : 0.f;
            float f1 = vr[2 * i + 1] ? ap[2 * i + 1][k0 + t]     : 0.f;
            float f2 = vr[2 * i]     ? ap[2 * i][k0 + t + 4]     : 0.f;
            float f3 = vr[2 * i + 1] ? ap[2 * i + 1][k0 + t + 4] : 0.f;
            split_tf32(f0, ah[i][0], al[i][0]);
            split_tf32(f1, ah[i][1], al[i][1]);
            split_tf32(f2, ah[i][2], al[i][2]);
            split_tf32(f3, ah[i][3], al[i][3]);
        }
#pragma unroll
        for (int j = 0; j < 8; j++) {
            float bv0 = B[(long long)(k0 + t) * DD + nb + 8 * j + g];
            float bv1 = B[(long long)(k0 + t + 4) * DD + nb + 8 * j + g];
            uint32_t bh[2], bl[2];
            split_tf32(bv0, bh[0], bl[0]);
            split_tf32(bv1, bh[1], bl[1]);
#pragma unroll
            for (int i = 0; i < 2; i++) {
                mma8(acc[i][j], ah[i], bh);
                mma8(acc[i][j], ah[i], bl);
                mma8(acc[i][j], al[i], bh);
            }
        }
    }

#pragma unroll
    for (int i = 0; i < 2; i++)
#pragma unroll
        for (int j = 0; j < 8; j++) {
            int c0 = nb + 8 * j + 2 * t;
            if (vr[2 * i]) {
                C[(long long)rows[2 * i] * DD + c0]     = acc[i][j][0];
                C[(long long)rows[2 * i] * DD + c0 + 1] = acc[i][j][1];
            }
            if (vr[2 * i + 1]) {
                C[(long long)rows[2 * i + 1] * DD + c0]     = acc[i][j][2];
                C[(long long)rows[2 * i + 1] * DD + c0 + 1] = acc[i][j][3];
            }
        }
}

// ---------------- fused aggregate: self-loop + CSR gather + bias + relu --------
__global__ __launch_bounds__(256) void k_aggregate(const float* __restrict__ tmp,
                                                   float* __restrict__ out,
                                                   const float* __restrict__ bias) {
    int node = (int)(((long long)blockIdx.x * blockDim.x + threadIdx.x) >> 5);
    int lane = threadIdx.x & 31;
    if (node >= NN) return;

    float di = g_dinv[node];
    float ws = di * di;
    const float4* r = (const float4*)(tmp + (long long)node * DD);
    float4 v0 = r[lane], v1 = r[lane + 32];
    float4 a0 = {v0.x * ws, v0.y * ws, v0.z * ws, v0.w * ws};
    float4 a1 = {v1.x * ws, v1.y * ws, v1.z * ws, v1.w * ws};

    int p = g_rowptr[node], pe = g_rowptr[node + 1];
    for (; p < pe; ++p) {
        int s = g_csr_src[p];
        float w = g_csr_w[p];
        const float4* rs = (const float4*)(tmp + (long long)s * DD);
        float4 u0 = rs[lane], u1 = rs[lane + 32];
        a0.x += w * u0.x; a0.y += w * u0.y; a0.z += w * u0.z; a0.w += w * u0.w;
        a1.x += w * u1.x; a1.y += w * u1.y; a1.z += w * u1.z; a1.w += w * u1.w;
    }

    float4 b0 = ((const float4*)bias)[lane];
    float4 b1 = ((const float4*)bias)[lane + 32];
    a0.x = fmaxf(a0.x + b0.x, 0.f); a0.y = fmaxf(a0.y + b0.y, 0.f);
    a0.z = fmaxf(a0.z + b0.z, 0.f); a0.w = fmaxf(a0.w + b0.w, 0.f);
    a1.x = fmaxf(a1.x + b1.x, 0.f); a1.y = fmaxf(a1.y + b1.y, 0.f);
    a1.z = fmaxf(a1.z + b1.z, 0.f); a1.w = fmaxf(a1.w + b1.w, 0.f);

    float4* o = (float4*)(out + (long long)node * DD);
    o[lane] = a0;
    o[lane + 32] = a1;
}

// ---------------- pool: batch is sorted -> segmented per-block sums ------------
__global__ void k_pool2(const float* __restrict__ h, const void* __restrict__ batch) {
    int col = threadIdx.x;            // 256 threads = 256 cols
    int n0 = blockIdx.x * 128;
    int n1 = min(n0 + 128, NN);
    int is32 = g_flags[1];
    int cur = (int)fetch_idx(batch, n0, is32);
    float acc = 0.f;
    int cnt = 0;
    for (int n = n0; n < n1; n++) {
        int gid = (int)fetch_idx(batch, n, is32);
        if (gid != cur) {
            atomicAdd(&g_pool[cur * DD + col], acc);
            if (col == 0) atomicAdd(&g_cnt[cur], (float)cnt);
            acc = 0.f; cnt = 0; cur = gid;
        }
        acc += h[(long long)n * DD + col];
        cnt++;
    }
    atomicAdd(&g_pool[cur * DD + col], acc);
    if (col == 0) atomicAdd(&g_cnt[cur], (float)cnt);
}

__global__ void k_fc(const float* __restrict__ Wfc, const float* __restrict__ bfc,
                     float* __restrict__ out) {
    int tt = blockIdx.x * blockDim.x + threadIdx.x;
    if (tt >= GG * DOUT) return;
    int g = tt >> 4, o = tt & 15;
    float inv = 1.0f / fmaxf(g_cnt[g], 1.0f);
    float acc = 0.f;
#pragma unroll 8
    for (int k = 0; k < DD; k++) acc += g_pool[g * DD + k] * Wfc[k * DOUT + o];
    out[tt] = acc * inv + bfc[o];
}

// ---------------- launch ----------------
extern "C" void kernel_launch(void* const* d_in, const int* in_sizes, int n_in,
                              void* d_out, int out_size) {
    const float* x     = (const float*)d_in[0];
    const void*  ei    = d_in[1];
    const void*  batch = d_in[2];
    const float* W1 = (const float*)d_in[3];  const float* b1 = (const float*)d_in[4];
    const float* W2 = (const float*)d_in[5];  const float* b2 = (const float*)d_in[6];
    const float* W3 = (const float*)d_in[7];  const float* b3 = (const float*)d_in[8];
    const float* Wfc = (const float*)d_in[9]; const float* bfc = (const float*)d_in[10];
    float* out = (float*)d_out;

    long long E = in_sizes[1] / 2;

    float *S0, *S1;
    cudaGetSymbolAddress((void**)&S0, g_S0);
    cudaGetSymbolAddress((void**)&S1, g_S1);

    k_zero_misc<<<(NN + 255) / 256, 256>>>();
    k_detect<<<(int)((in_sizes[1] / 2 + 255) / 256), 256>>>((const unsigned*)ei,
                                                            (long long)in_sizes[1], 0);
    k_detect<<<(int)((in_sizes[2] / 2 + 255) / 256), 256>>>((const unsigned*)batch,
                                                            (long long)in_sizes[2], 1);
    k_count<<<(int)((E + 255) / 256), 256>>>(ei, E);
    k_dinv<<<(NN + 255) / 256, 256>>>();
    k_scan<<<1, 1024>>>();
    k_fill<<<(int)((E + 255) / 256), 256>>>(ei, E);

    dim3 gemm_grid((NN + 255) / 256, 4);
    const float* Ws[3] = {W1, W2, W3};
    const float* bs[3] = {b1, b2, b3};
    const float* in = x;
    for (int l = 0; l < 3; l++) {
        k_gemm_tf32<<<gemm_grid, 256>>>(in, Ws[l], S0, NN);
        k_aggregate<<<(NN * 32 + 255) / 256, 256>>>(S0, S1, bs[l]);
        in = S1;
    }

    k_pool2<<<(NN + 127) / 128, 256>>>(S1, batch);
    k_fc<<<(GG * DOUT + 255) / 256, 256>>>(Wfc, bfc, out);
}

// round 3
// speedup vs baseline: 2.7801x; 1.0435x over previous
#include <cuda_runtime.h>
#include <cstdint>

#define NN 50000
#define EE 400000
#define DD 256
#define GG 64
#define DOUT 16

// ---------------- static scratch ----------------
__device__ float g_S0[NN * DD];       // tmp = in @ W
__device__ float g_S1[NN * DD];       // layer output
__device__ int   g_degi[NN];
__device__ float g_dinv[NN];
__device__ int   g_rowptr[NN + 1];
__device__ int   g_cursor[NN];
__device__ int   g_csr_src[EE];
__device__ float g_csr_w[EE];
__device__ float g_pool[GG * DD];
__device__ float g_cnt[GG];
__device__ int   g_flags[2];          // [0]: edge_index is32, [1]: batch is32

// ---------------- index dtype ----------------
__device__ __forceinline__ long long fetch_idx(const void* p, long long i, int is32) {
    if (is32) return (long long)((const int*)p)[i];
    return ((const long long*)p)[i];
}

__global__ void k_zero_misc() {
    int i = blockIdx.x * blockDim.x + threadIdx.x;
    if (i < NN) g_degi[i] = 0;
    if (i < GG * DD) g_pool[i] = 0.f;
    if (i < GG) g_cnt[i] = 0.f;
    if (i < 2) g_flags[i] = 0;
}

// int64 values < 2^31 have zero high words; int32 buffers have nonzero odd words.
__global__ void k_detect(const unsigned* __restrict__ w, long long nwords, int which) {
    long long i = 2ll * ((long long)blockIdx.x * blockDim.x + threadIdx.x) + 1;
    unsigned v = (i < nwords) ? w[i] : 0u;
#pragma unroll
    for (int o = 16; o > 0; o >>= 1) v |= __shfl_xor_sync(0xffffffffu, v, o);
    if ((threadIdx.x & 31) == 0 && v) atomicOr(&g_flags[which], 1);
}

__global__ void k_count(const void* __restrict__ ei, long long E) {
    long long e = (long long)blockIdx.x * blockDim.x + threadIdx.x;
    if (e >= E) return;
    int is32 = g_flags[0];
    long long d = fetch_idx(ei, E + e, is32);
    atomicAdd(&g_degi[d], 1);
}

__global__ void k_dinv() {
    int n = blockIdx.x * blockDim.x + threadIdx.x;
    if (n < NN) g_dinv[n] = rsqrtf((float)g_degi[n] + 1.0f);   // +1 self loop
}

// Single-block exclusive scan over 50000 degrees -> row_ptr + cursor
__global__ void k_scan() {
    __shared__ int part[1024];
    const int CH = (NN + 1023) / 1024;   // 49
    int t = threadIdx.x;
    int beg = t * CH, end = min(beg + CH, NN);
    int s = 0;
    for (int i = beg; i < end; i++) s += g_degi[i];
    part[t] = s;
    __syncthreads();
    for (int off = 1; off < 1024; off <<= 1) {
        int v = (t >= off) ? part[t - off] : 0;
        __syncthreads();
        part[t] += v;
        __syncthreads();
    }
    int excl = (t == 0) ? 0 : part[t - 1];
    for (int i = beg; i < end; i++) {
        g_rowptr[i] = excl;
        g_cursor[i] = excl;
        excl += g_degi[i];
    }
    if (t == 1023) g_rowptr[NN] = part[1023];
}

__global__ void k_fill(const void* __restrict__ ei, long long E) {
    long long e = (long long)blockIdx.x * blockDim.x + threadIdx.x;
    if (e >= E) return;
    int is32 = g_flags[0];
    int s = (int)fetch_idx(ei, e, is32);
    int d = (int)fetch_idx(ei, E + e, is32);
    int pos = atomicAdd(&g_cursor[d], 1);
    g_csr_src[pos] = s;
    g_csr_w[pos] = g_dinv[s] * g_dinv[d];
}

// ---------------- 3xTF32 tensor-core GEMM v2 ----------------
// C[M,256] = A[M,256] @ B[256,256]. One block: 128 rows x all 256 cols.
// 8 warps (2m x 4n), warp tile 64x64, BK=8, smem-staged pre-split operands.
__device__ __forceinline__ void split_tf32(float x, uint32_t& hi, uint32_t& lo) {
    asm("cvt.rna.tf32.f32 %0, %1;" : "=r"(hi) : "f"(x));
    float r = x - __uint_as_float(hi);
    asm("cvt.rna.tf32.f32 %0, %1;" : "=r"(lo) : "f"(r));
}

__device__ __forceinline__ void mma8(float* c, const uint32_t* a, const uint32_t* b) {
    asm volatile(
        "mma.sync.aligned.m16n8k8.row.col.f32.tf32.tf32.f32 "
        "{%0,%1,%2,%3}, {%4,%5,%6,%7}, {%8,%9}, {%0,%1,%2,%3};"
        : "+f"(c[0]), "+f"(c[1]), "+f"(c[2]), "+f"(c[3])
        : "r"(a[0]), "r"(a[1]), "r"(a[2]), "r"(a[3]), "r"(b[0]), "r"(b[1]));
}

#define APAD 12    // As row stride (words): banks 12g+t distinct across a warp
#define BPAD 264   // Bs row stride (words): banks 8t+n distinct across a warp

__global__ __launch_bounds__(256, 1) void k_gemm2(const float* __restrict__ A,
                                                  const float* __restrict__ B,
                                                  float* __restrict__ C, int M) {
    __shared__ uint32_t As[2][128][APAD];  // [hi/lo][row][k]
    __shared__ uint32_t Bs[2][8][BPAD];    // [hi/lo][k][n]

    int tid = threadIdx.x, wid = tid >> 5, lane = tid & 31;
    int g = lane >> 2, t = lane & 3;
    int wm = wid & 1, wn = wid >> 1;       // warp grid 2(m) x 4(n)
    int bm = blockIdx.x * 128;

    // staging thread mapping
    int a_row = tid >> 1;                  // 0..127
    int a_kk  = (tid & 1) * 4;             // 0 or 4
    int b_k   = tid >> 5;                  // 0..7 (warp id)
    int b_n   = lane * 4;                  // 0..124 (plus +128 second vec)

    long long a_base = (long long)(bm + a_row) * DD + a_kk;
    bool a_ok = (bm + a_row) < M;

    float4 pa, pb0, pb1;
    const float4 z4 = make_float4(0.f, 0.f, 0.f, 0.f);
    pa  = a_ok ? *(const float4*)(A + a_base) : z4;
    pb0 = *(const float4*)(B + (long long)b_k * DD + b_n);
    pb1 = *(const float4*)(B + (long long)b_k * DD + b_n + 128);

    float acc[4][8][4];
#pragma unroll
    for (int i = 0; i < 4; i++)
#pragma unroll
        for (int j = 0; j < 8; j++)
#pragma unroll
            for (int q = 0; q < 4; q++) acc[i][j][q] = 0.f;

    for (int k0 = 0; k0 < DD / 8; k0++) {
        // split prefetched regs -> smem
        {
            uint4 h, l;
            split_tf32(pa.x, h.x, l.x); split_tf32(pa.y, h.y, l.y);
            split_tf32(pa.z, h.z, l.z); split_tf32(pa.w, h.w, l.w);
            *(uint4*)&As[0][a_row][a_kk] = h;
            *(uint4*)&As[1][a_row][a_kk] = l;
            split_tf32(pb0.x, h.x, l.x); split_tf32(pb0.y, h.y, l.y);
            split_tf32(pb0.z, h.z, l.z); split_tf32(pb0.w, h.w, l.w);
            *(uint4*)&Bs[0][b_k][b_n] = h;
            *(uint4*)&Bs[1][b_k][b_n] = l;
            split_tf32(pb1.x, h.x, l.x); split_tf32(pb1.y, h.y, l.y);
            split_tf32(pb1.z, h.z, l.z); split_tf32(pb1.w, h.w, l.w);
            *(uint4*)&Bs[0][b_k][b_n + 128] = h;
            *(uint4*)&Bs[1][b_k][b_n + 128] = l;
        }
        __syncthreads();

        // prefetch next k-slab into registers (overlaps with compute below)
        if (k0 + 1 < DD / 8) {
            int kb = (k0 + 1) * 8;
            pa  = a_ok ? *(const float4*)(A + a_base + kb) : z4;
            pb0 = *(const float4*)(B + (long long)(kb + b_k) * DD + b_n);
            pb1 = *(const float4*)(B + (long long)(kb + b_k) * DD + b_n + 128);
        }

        // B fragments once per warp, reused across 4 m-subtiles
        uint32_t bh[8][2], bl[8][2];
#pragma unroll
        for (int j = 0; j < 8; j++) {
            int n = wn * 64 + 8 * j + g;
            bh[j][0] = Bs[0][t][n];     bh[j][1] = Bs[0][t + 4][n];
            bl[j][0] = Bs[1][t][n];     bl[j][1] = Bs[1][t + 4][n];
        }
#pragma unroll
        for (int i = 0; i < 4; i++) {
            int r = wm * 64 + i * 16;
            uint32_t ah[4], al[4];
            ah[0] = As[0][r + g][t];      ah[1] = As[0][r + g + 8][t];
            ah[2] = As[0][r + g][t + 4];  ah[3] = As[0][r + g + 8][t + 4];
            al[0] = As[1][r + g][t];      al[1] = As[1][r + g + 8][t];
            al[2] = As[1][r + g][t + 4];  al[3] = As[1][r + g + 8][t + 4];
#pragma unroll
            for (int j = 0; j < 8; j++) {
                mma8(acc[i][j], ah, bh[j]);
                mma8(acc[i][j], ah, bl[j]);
                mma8(acc[i][j], al, bh[j]);
            }
        }
        __syncthreads();
    }

#pragma unroll
    for (int i = 0; i < 4; i++)
#pragma unroll
        for (int j = 0; j < 8; j++) {
            int row0 = bm + wm * 64 + i * 16 + g;
            int col  = wn * 64 + 8 * j + 2 * t;
            if (row0 < M) {
                float2 v = {acc[i][j][0], acc[i][j][1]};
                *(float2*)(C + (long long)row0 * DD + col) = v;
            }
            int row1 = row0 + 8;
            if (row1 < M) {
                float2 v = {acc[i][j][2], acc[i][j][3]};
                *(float2*)(C + (long long)row1 * DD + col) = v;
            }
        }
}

// ---------------- fused aggregate: self-loop + CSR gather + bias + relu --------
__global__ __launch_bounds__(256) void k_aggregate(const float* __restrict__ tmp,
                                                   float* __restrict__ out,
                                                   const float* __restrict__ bias) {
    int node = (int)(((long long)blockIdx.x * blockDim.x + threadIdx.x) >> 5);
    int lane = threadIdx.x & 31;
    if (node >= NN) return;

    float di = g_dinv[node];
    float ws = di * di;
    const float4* r = (const float4*)(tmp + (long long)node * DD);
    float4 v0 = r[lane], v1 = r[lane + 32];
    float4 a0 = {v0.x * ws, v0.y * ws, v0.z * ws, v0.w * ws};
    float4 a1 = {v1.x * ws, v1.y * ws, v1.z * ws, v1.w * ws};

    int p = g_rowptr[node], pe = g_rowptr[node + 1];
    for (; p < pe; ++p) {
        int s = g_csr_src[p];
        float w = g_csr_w[p];
        const float4* rs = (const float4*)(tmp + (long long)s * DD);
        float4 u0 = rs[lane], u1 = rs[lane + 32];
        a0.x += w * u0.x; a0.y += w * u0.y; a0.z += w * u0.z; a0.w += w * u0.w;
        a1.x += w * u1.x; a1.y += w * u1.y; a1.z += w * u1.z; a1.w += w * u1.w;
    }

    float4 b0 = ((const float4*)bias)[lane];
    float4 b1 = ((const float4*)bias)[lane + 32];
    a0.x = fmaxf(a0.x + b0.x, 0.f); a0.y = fmaxf(a0.y + b0.y, 0.f);
    a0.z = fmaxf(a0.z + b0.z, 0.f); a0.w = fmaxf(a0.w + b0.w, 0.f);
    a1.x = fmaxf(a1.x + b1.x, 0.f); a1.y = fmaxf(a1.y + b1.y, 0.f);
    a1.z = fmaxf(a1.z + b1.z, 0.f); a1.w = fmaxf(a1.w + b1.w, 0.f);

    float4* o = (float4*)(out + (long long)node * DD);
    o[lane] = a0;
    o[lane + 32] = a1;
}

// ---------------- pool: batch is sorted -> segmented per-block sums ------------
__global__ void k_pool2(const float* __restrict__ h, const void* __restrict__ batch) {
    int col = threadIdx.x;            // 256 threads = 256 cols
    int n0 = blockIdx.x * 128;
    int n1 = min(n0 + 128, NN);
    int is32 = g_flags[1];
    int cur = (int)fetch_idx(batch, n0, is32);
    float acc = 0.f;
    int cnt = 0;
    for (int n = n0; n < n1; n++) {
        int gid = (int)fetch_idx(batch, n, is32);
        if (gid != cur) {
            atomicAdd(&g_pool[cur * DD + col], acc);
            if (col == 0) atomicAdd(&g_cnt[cur], (float)cnt);
            acc = 0.f; cnt = 0; cur = gid;
        }
        acc += h[(long long)n * DD + col];
        cnt++;
    }
    atomicAdd(&g_pool[cur * DD + col], acc);
    if (col == 0) atomicAdd(&g_cnt[cur], (float)cnt);
}

__global__ void k_fc(const float* __restrict__ Wfc, const float* __restrict__ bfc,
                     float* __restrict__ out) {
    int tt = blockIdx.x * blockDim.x + threadIdx.x;
    if (tt >= GG * DOUT) return;
    int g = tt >> 4, o = tt & 15;
    float inv = 1.0f / fmaxf(g_cnt[g], 1.0f);
    float acc = 0.f;
#pragma unroll 8
    for (int k = 0; k < DD; k++) acc += g_pool[g * DD + k] * Wfc[k * DOUT + o];
    out[tt] = acc * inv + bfc[o];
}

// ---------------- launch ----------------
extern "C" void kernel_launch(void* const* d_in, const int* in_sizes, int n_in,
                              void* d_out, int out_size) {
    const float* x     = (const float*)d_in[0];
    const void*  ei    = d_in[1];
    const void*  batch = d_in[2];
    const float* W1 = (const float*)d_in[3];  const float* b1 = (const float*)d_in[4];
    const float* W2 = (const float*)d_in[5];  const float* b2 = (const float*)d_in[6];
    const float* W3 = (const float*)d_in[7];  const float* b3 = (const float*)d_in[8];
    const float* Wfc = (const float*)d_in[9]; const float* bfc = (const float*)d_in[10];
    float* out = (float*)d_out;

    long long E = in_sizes[1] / 2;

    float *S0, *S1;
    cudaGetSymbolAddress((void**)&S0, g_S0);
    cudaGetSymbolAddress((void**)&S1, g_S1);

    k_zero_misc<<<(NN + 255) / 256, 256>>>();
    k_detect<<<(int)((in_sizes[1] / 2 + 255) / 256), 256>>>((const unsigned*)ei,
                                                            (long long)in_sizes[1], 0);
    k_detect<<<(int)((in_sizes[2] / 2 + 255) / 256), 256>>>((const unsigned*)batch,
                                                            (long long)in_sizes[2], 1);
    k_count<<<(int)((E + 255) / 256), 256>>>(ei, E);
    k_dinv<<<(NN + 255) / 256, 256>>>();
    k_scan<<<1, 1024>>>();
    k_fill<<<(int)((E + 255) / 256), 256>>>(ei, E);

    int gemm_blocks = (NN + 127) / 128;    // 391
    const float* Ws[3] = {W1, W2, W3};
    const float* bs[3] = {b1, b2, b3};
    const float* in = x;
    for (int l = 0; l < 3; l++) {
        k_gemm2<<<gemm_blocks, 256>>>(in, Ws[l], S0, NN);
        k_aggregate<<<(NN * 32 + 255) / 256, 256>>>(S0, S1, bs[l]);
        in = S1;
    }

    k_pool2<<<(NN + 127) / 128, 256>>>(S1, batch);
    k_fc<<<(GG * DOUT + 255) / 256, 256>>>(Wfc, bfc, out);
}